// round 2
// baseline (speedup 1.0000x reference)
#include <cuda_runtime.h>
#include <math.h>

#define BB 2
#define TT 2048
#define DD 1024
#define HH 16
#define LL 8
#define II 4096
#define MROWS (BB*TT)          // 4096
#define MASK_BIAS (-10000.0f)

// -------- scratch (no allocations allowed) --------
static __device__ float g_H  [(size_t)BB*TT*DD];     // residual stream
static __device__ float g_X  [(size_t)BB*TT*DD];     // LN output
static __device__ float g_QKV[(size_t)BB*TT*3*DD];
static __device__ float g_CTX[(size_t)BB*TT*DD];
static __device__ float g_FF [(size_t)BB*TT*II];

// ---------------------------------------------------------------- copy
__global__ void copy_kernel(const float4* __restrict__ src, float4* __restrict__ dst, int n4) {
    int i = blockIdx.x * blockDim.x + threadIdx.x;
    if (i < n4) dst[i] = src[i];
}

// ---------------------------------------------------------------- layernorm (one row / block, 256 thr, D=1024)
__global__ void ln_kernel(const float* __restrict__ in, const float* __restrict__ w,
                          const float* __restrict__ bsc, float* __restrict__ out) {
    int row = blockIdx.x;
    int t = threadIdx.x;
    const float4* x4 = (const float4*)(in + (size_t)row * DD);
    float4 v = x4[t];
    float s = v.x + v.y + v.z + v.w;
    float q = v.x*v.x + v.y*v.y + v.z*v.z + v.w*v.w;
    #pragma unroll
    for (int o = 16; o; o >>= 1) {
        s += __shfl_xor_sync(0xffffffffu, s, o);
        q += __shfl_xor_sync(0xffffffffu, q, o);
    }
    __shared__ float ss[8], sq[8];
    __shared__ float red[2];
    int wid = t >> 5, lane = t & 31;
    if (lane == 0) { ss[wid] = s; sq[wid] = q; }
    __syncthreads();
    if (t == 0) {
        float S = 0.f, Q = 0.f;
        #pragma unroll
        for (int i = 0; i < 8; i++) { S += ss[i]; Q += sq[i]; }
        float mean = S * (1.0f / DD);
        float var  = Q * (1.0f / DD) - mean * mean;
        red[0] = mean;
        red[1] = rsqrtf(var + 1e-5f);
    }
    __syncthreads();
    float mean = red[0], inv = red[1];
    float4 wv = ((const float4*)w)[t];
    float4 bv = ((const float4*)bsc)[t];
    float4 o;
    o.x = (v.x - mean) * inv * wv.x + bv.x;
    o.y = (v.y - mean) * inv * wv.y + bv.y;
    o.z = (v.z - mean) * inv * wv.z + bv.z;
    o.w = (v.w - mean) * inv * wv.w + bv.w;
    ((float4*)(out + (size_t)row * DD))[t] = o;
}

// ---------------------------------------------------------------- SGEMM 128x128x8, 256 thr, 8x8/thread
// C[m][n] = A[m][:] @ B[:][n] + bias[n] (+ res[m][n]) (+relu)
template<bool RES, bool RELU>
__global__ __launch_bounds__(256, 2)
void gemm_kernel(const float* __restrict__ A, const float* __restrict__ B,
                 const float* __restrict__ bias, const float* __restrict__ res,
                 float* __restrict__ C, int N, int K) {
    const int M0 = blockIdx.y * 128, N0 = blockIdx.x * 128;
    __shared__ float As[8][132];   // A^T tile
    __shared__ float Bs[8][128];
    const int tid = threadIdx.x;
    const int ty = tid >> 4, tx = tid & 15;

    float acc[8][8];
    #pragma unroll
    for (int i = 0; i < 8; i++)
        #pragma unroll
        for (int j = 0; j < 8; j++) acc[i][j] = 0.f;

    const int arow = tid >> 1, acol = (tid & 1) * 4;
    const int brow = tid >> 5, bcol = (tid & 31) * 4;
    const float* Aptr = A + (size_t)(M0 + arow) * K + acol;
    const float* Bptr = B + (size_t)brow * N + N0 + bcol;

    for (int k0 = 0; k0 < K; k0 += 8) {
        float4 av = *(const float4*)(Aptr + k0);
        float4 bv = *(const float4*)(Bptr + (size_t)k0 * N);
        As[acol + 0][arow] = av.x;
        As[acol + 1][arow] = av.y;
        As[acol + 2][arow] = av.z;
        As[acol + 3][arow] = av.w;
        *(float4*)&Bs[brow][bcol] = bv;
        __syncthreads();
        #pragma unroll
        for (int kk = 0; kk < 8; kk++) {
            float4 a0 = *(const float4*)&As[kk][ty * 8];
            float4 a1 = *(const float4*)&As[kk][ty * 8 + 4];
            float4 b0 = *(const float4*)&Bs[kk][tx * 8];
            float4 b1 = *(const float4*)&Bs[kk][tx * 8 + 4];
            float a[8] = {a0.x, a0.y, a0.z, a0.w, a1.x, a1.y, a1.z, a1.w};
            float b[8] = {b0.x, b0.y, b0.z, b0.w, b1.x, b1.y, b1.z, b1.w};
            #pragma unroll
            for (int i = 0; i < 8; i++)
                #pragma unroll
                for (int j = 0; j < 8; j++) acc[i][j] += a[i] * b[j];
        }
        __syncthreads();
    }

    float4 bia0 = *(const float4*)&bias[N0 + tx * 8];
    float4 bia1 = *(const float4*)&bias[N0 + tx * 8 + 4];
    float bb[8] = {bia0.x, bia0.y, bia0.z, bia0.w, bia1.x, bia1.y, bia1.z, bia1.w};
    #pragma unroll
    for (int i = 0; i < 8; i++) {
        int m = M0 + ty * 8 + i;
        float* crow = C + (size_t)m * N + N0 + tx * 8;
        float v[8];
        #pragma unroll
        for (int j = 0; j < 8; j++) v[j] = acc[i][j] + bb[j];
        if (RES) {
            const float* rrow = res + (size_t)m * N + N0 + tx * 8;
            float4 r0 = *(const float4*)rrow;
            float4 r1 = *(const float4*)(rrow + 4);
            v[0] += r0.x; v[1] += r0.y; v[2] += r0.z; v[3] += r0.w;
            v[4] += r1.x; v[5] += r1.y; v[6] += r1.z; v[7] += r1.w;
        }
        if (RELU) {
            #pragma unroll
            for (int j = 0; j < 8; j++) v[j] = fmaxf(v[j], 0.f);
        }
        *(float4*)crow       = make_float4(v[0], v[1], v[2], v[3]);
        *(float4*)(crow + 4) = make_float4(v[4], v[5], v[6], v[7]);
    }
}

// ---------------------------------------------------------------- flash attention (fp32)
// grid (T/32, H, B), 256 thr. BQ=32, BK=64, hd=64. Online softmax.
__global__ __launch_bounds__(256)
void attn_kernel(const float* __restrict__ qkv, const float* __restrict__ amask,
                 float* __restrict__ ctx) {
    const int q0 = blockIdx.x * 32;
    const int h = blockIdx.y, b = blockIdx.z;
    const int tid = threadIdx.x;

    __shared__ float QsT[64][36];        // [d][q]
    __shared__ float KV[64 * 68];        // phase1: K^T [d][k] stride 68; phase3: V [k][d] stride 68
    __shared__ float Ss[32][68];         // scores / probs
    __shared__ float row_m[32], row_l[32], row_a[32];
    __shared__ float madd[64];

    // load Q^T
    for (int idx = tid; idx < 32 * 64; idx += 256) {
        int q = idx >> 6, d = idx & 63;
        QsT[d][q] = qkv[(size_t)(b * TT + q0 + q) * (3 * DD) + h * 64 + d];
    }
    if (tid < 32) { row_m[tid] = -3.0e38f; row_l[tid] = 0.f; }

    float o[2][4] = {{0.f,0.f,0.f,0.f},{0.f,0.f,0.f,0.f}};
    const int oq = (tid >> 4) * 2, od = (tid & 15) * 4;   // O / S microtile mapping
    const int srow = tid >> 3, sseg = tid & 7;            // softmax mapping (8 lanes / row)
    __syncthreads();

    const int kend = q0 + 32;
    for (int k0 = 0; k0 < kend; k0 += 64) {
        // ---- load K^T and additive mask ----
        for (int idx = tid; idx < 64 * 64; idx += 256) {
            int kt = idx >> 6, d = idx & 63;
            KV[d * 68 + kt] = qkv[(size_t)(b * TT + k0 + kt) * (3 * DD) + DD + h * 64 + d];
        }
        if (tid < 64) madd[tid] = (1.0f - amask[b * TT + k0 + tid]) * MASK_BIAS;
        __syncthreads();

        // ---- S = Q @ K^T (2x4 microtile) ----
        float s[2][4] = {{0.f,0.f,0.f,0.f},{0.f,0.f,0.f,0.f}};
        #pragma unroll 8
        for (int d = 0; d < 64; d++) {
            float2 qv = *(const float2*)&QsT[d][oq];
            float4 kv = *(const float4*)&KV[d * 68 + od];
            s[0][0] += qv.x * kv.x; s[0][1] += qv.x * kv.y;
            s[0][2] += qv.x * kv.z; s[0][3] += qv.x * kv.w;
            s[1][0] += qv.y * kv.x; s[1][1] += qv.y * kv.y;
            s[1][2] += qv.y * kv.z; s[1][3] += qv.y * kv.w;
        }
        // mask + scale + store
        #pragma unroll
        for (int i = 0; i < 2; i++) {
            int qg = q0 + oq + i;
            float vv[4];
            #pragma unroll
            for (int j = 0; j < 4; j++) {
                int kg = k0 + od + j;
                float v = (kg <= qg) ? s[i][j] * 0.125f : MASK_BIAS;
                vv[j] = v + madd[od + j];
            }
            *(float4*)&Ss[oq + i][od] = make_float4(vv[0], vv[1], vv[2], vv[3]);
        }
        __syncthreads();

        // ---- online softmax (8 lanes per row) ----
        {
            float* sr = &Ss[srow][sseg * 8];
            float lm = sr[0];
            #pragma unroll
            for (int j = 1; j < 8; j++) lm = fmaxf(lm, sr[j]);
            lm = fmaxf(lm, __shfl_xor_sync(0xffffffffu, lm, 1, 8));
            lm = fmaxf(lm, __shfl_xor_sync(0xffffffffu, lm, 2, 8));
            lm = fmaxf(lm, __shfl_xor_sync(0xffffffffu, lm, 4, 8));
            float m_old = row_m[srow];
            float m_new = fmaxf(m_old, lm);
            float ls = 0.f;
            #pragma unroll
            for (int j = 0; j < 8; j++) {
                float p = __expf(sr[j] - m_new);
                sr[j] = p;
                ls += p;
            }
            ls += __shfl_xor_sync(0xffffffffu, ls, 1, 8);
            ls += __shfl_xor_sync(0xffffffffu, ls, 2, 8);
            ls += __shfl_xor_sync(0xffffffffu, ls, 4, 8);
            if (sseg == 0) {
                float alpha = __expf(m_old - m_new);
                row_l[srow] = row_l[srow] * alpha + ls;
                row_m[srow] = m_new;
                row_a[srow] = alpha;
            }
        }
        __syncthreads();

        // ---- rescale O; load V (overwrites KV) ----
        {
            float a0 = row_a[oq], a1 = row_a[oq + 1];
            #pragma unroll
            for (int j = 0; j < 4; j++) { o[0][j] *= a0; o[1][j] *= a1; }
        }
        for (int idx = tid; idx < 64 * 64; idx += 256) {
            int kt = idx >> 6, d = idx & 63;
            KV[kt * 68 + d] = qkv[(size_t)(b * TT + k0 + kt) * (3 * DD) + 2 * DD + h * 64 + d];
        }
        __syncthreads();

        // ---- O += P @ V ----
        #pragma unroll 8
        for (int k = 0; k < 64; k++) {
            float p0 = Ss[oq][k], p1 = Ss[oq + 1][k];
            float4 vv = *(const float4*)&KV[k * 68 + od];
            o[0][0] += p0 * vv.x; o[0][1] += p0 * vv.y;
            o[0][2] += p0 * vv.z; o[0][3] += p0 * vv.w;
            o[1][0] += p1 * vv.x; o[1][1] += p1 * vv.y;
            o[1][2] += p1 * vv.z; o[1][3] += p1 * vv.w;
        }
        __syncthreads();
    }

    float inv0 = 1.f / row_l[oq];
    float inv1 = 1.f / row_l[oq + 1];
    float* c0 = ctx + (size_t)(b * TT + q0 + oq) * DD + h * 64 + od;
    float* c1 = ctx + (size_t)(b * TT + q0 + oq + 1) * DD + h * 64 + od;
    *(float4*)c0 = make_float4(o[0][0]*inv0, o[0][1]*inv0, o[0][2]*inv0, o[0][3]*inv0);
    *(float4*)c1 = make_float4(o[1][0]*inv1, o[1][1]*inv1, o[1][2]*inv1, o[1][3]*inv1);
}

// ---------------------------------------------------------------- launch
extern "C" void kernel_launch(void* const* d_in, const int* in_sizes, int n_in,
                              void* d_out, int out_size) {
    const float* emb   = (const float*)d_in[0];
    const float* amask = (const float*)d_in[1];
    const float* ln1w  = (const float*)d_in[2];
    const float* ln1b  = (const float*)d_in[3];
    const float* attnw = (const float*)d_in[4];
    const float* attnb = (const float*)d_in[5];
    const float* projw = (const float*)d_in[6];
    const float* projb = (const float*)d_in[7];
    const float* ln2w  = (const float*)d_in[8];
    const float* ln2b  = (const float*)d_in[9];
    const float* fcw   = (const float*)d_in[10];
    const float* fcb   = (const float*)d_in[11];
    const float* fcpw  = (const float*)d_in[12];
    const float* fcpb  = (const float*)d_in[13];
    const float* lnfw  = (const float*)d_in[14];
    const float* lnfb  = (const float*)d_in[15];
    float* out = (float*)d_out;

    float *H, *X, *QKV, *CTX, *FF;
    cudaGetSymbolAddress((void**)&H,   g_H);
    cudaGetSymbolAddress((void**)&X,   g_X);
    cudaGetSymbolAddress((void**)&QKV, g_QKV);
    cudaGetSymbolAddress((void**)&CTX, g_CTX);
    cudaGetSymbolAddress((void**)&FF,  g_FF);

    const int n4 = (MROWS * DD) / 4;
    copy_kernel<<<(n4 + 255) / 256, 256>>>((const float4*)emb, (float4*)H, n4);

    for (int l = 0; l < LL; l++) {
        const size_t wq = (size_t)l * DD * 3 * DD;
        const size_t wp = (size_t)l * DD * DD;
        const size_t wf = (size_t)l * DD * II;
        const size_t wg = (size_t)l * II * DD;

        ln_kernel<<<MROWS, 256>>>(H, ln1w + l * DD, ln1b + l * DD, X);
        gemm_kernel<false, false><<<dim3(3 * DD / 128, MROWS / 128), 256>>>(
            X, attnw + wq, attnb + (size_t)l * 3 * DD, nullptr, QKV, 3 * DD, DD);
        attn_kernel<<<dim3(TT / 32, HH, BB), 256>>>(QKV, amask, CTX);
        gemm_kernel<true, false><<<dim3(DD / 128, MROWS / 128), 256>>>(
            CTX, projw + wp, projb + (size_t)l * DD, H, H, DD, DD);
        ln_kernel<<<MROWS, 256>>>(H, ln2w + l * DD, ln2b + l * DD, X);
        gemm_kernel<false, true><<<dim3(II / 128, MROWS / 128), 256>>>(
            X, fcw + wf, fcb + (size_t)l * II, nullptr, FF, II, DD);
        gemm_kernel<true, false><<<dim3(DD / 128, MROWS / 128), 256>>>(
            FF, fcpw + wg, fcpb + (size_t)l * DD, H, H, DD, II);
    }
    ln_kernel<<<MROWS, 256>>>(H, lnfw, lnfb, out);
}

// round 3
// speedup vs baseline: 1.0163x; 1.0163x over previous
#include <cuda_runtime.h>
#include <math.h>
#include <stdint.h>

#define BB 2
#define TT 2048
#define DD 1024
#define HH 16
#define LL 8
#define II 4096
#define MROWS (BB*TT)          // 4096
#define MASK_BIAS (-10000.0f)

// -------- scratch (no allocations allowed) --------
static __device__ float g_H  [(size_t)BB*TT*DD];     // residual stream
static __device__ float g_X  [(size_t)BB*TT*DD];     // LN output
static __device__ float g_QKV[(size_t)BB*TT*3*DD];
static __device__ float g_CTX[(size_t)BB*TT*DD];
static __device__ float g_FF [(size_t)BB*TT*II];

// ---------------------------------------------------------------- copy
__global__ void copy_kernel(const float4* __restrict__ src, float4* __restrict__ dst, int n4) {
    int i = blockIdx.x * blockDim.x + threadIdx.x;
    if (i < n4) dst[i] = src[i];
}

// ---------------------------------------------------------------- layernorm (one row / block, 256 thr, D=1024)
__global__ void ln_kernel(const float* __restrict__ in, const float* __restrict__ w,
                          const float* __restrict__ bsc, float* __restrict__ out) {
    int row = blockIdx.x;
    int t = threadIdx.x;
    const float4* x4 = (const float4*)(in + (size_t)row * DD);
    float4 v = x4[t];
    float s = v.x + v.y + v.z + v.w;
    float q = v.x*v.x + v.y*v.y + v.z*v.z + v.w*v.w;
    #pragma unroll
    for (int o = 16; o; o >>= 1) {
        s += __shfl_xor_sync(0xffffffffu, s, o);
        q += __shfl_xor_sync(0xffffffffu, q, o);
    }
    __shared__ float ss[8], sq[8];
    __shared__ float red[2];
    int wid = t >> 5, lane = t & 31;
    if (lane == 0) { ss[wid] = s; sq[wid] = q; }
    __syncthreads();
    if (t == 0) {
        float S = 0.f, Q = 0.f;
        #pragma unroll
        for (int i = 0; i < 8; i++) { S += ss[i]; Q += sq[i]; }
        float mean = S * (1.0f / DD);
        float var  = Q * (1.0f / DD) - mean * mean;
        red[0] = mean;
        red[1] = rsqrtf(var + 1e-5f);
    }
    __syncthreads();
    float mean = red[0], inv = red[1];
    float4 wv = ((const float4*)w)[t];
    float4 bv = ((const float4*)bsc)[t];
    float4 o;
    o.x = (v.x - mean) * inv * wv.x + bv.x;
    o.y = (v.y - mean) * inv * wv.y + bv.y;
    o.z = (v.z - mean) * inv * wv.z + bv.z;
    o.w = (v.w - mean) * inv * wv.w + bv.w;
    ((float4*)(out + (size_t)row * DD))[t] = o;
}

// ---------------------------------------------------------------- TF32 helpers
__device__ __forceinline__ void tf32_split(float x, uint32_t& hi, uint32_t& lo) {
    asm("cvt.rna.tf32.f32 %0, %1;" : "=r"(hi) : "f"(x));
    float r = x - __uint_as_float(hi);
    asm("cvt.rna.tf32.f32 %0, %1;" : "=r"(lo) : "f"(r));
}

__device__ __forceinline__ void mma8(float* c, const uint32_t* a, const uint32_t* b) {
    asm volatile(
        "mma.sync.aligned.m16n8k8.row.col.f32.tf32.tf32.f32 "
        "{%0,%1,%2,%3},{%4,%5,%6,%7},{%8,%9},{%0,%1,%2,%3};"
        : "+f"(c[0]), "+f"(c[1]), "+f"(c[2]), "+f"(c[3])
        : "r"(a[0]), "r"(a[1]), "r"(a[2]), "r"(a[3]), "r"(b[0]), "r"(b[1]));
}

// ---------------------------------------------------------------- 3xTF32 tensor-core GEMM
// 128x128 CTA tile, BK=32, 256 thr (8 warps, 2x4 grid, warp tile 64x32)
// C[m][n] = A[m][:] @ B[:][n] + bias[n] (+res[m][n]) (+relu)
template<bool RES, bool RELU>
__global__ __launch_bounds__(256)
void gemm_tc_kernel(const float* __restrict__ A, const float* __restrict__ B,
                    const float* __restrict__ bias, const float* __restrict__ res,
                    float* __restrict__ C, int N, int K) {
    __shared__ float As[128][40];   // [m][k], stride 40 -> frag bank = (8g+t) conflict-free
    __shared__ float Bs[32][136];   // [k][n], stride 136 -> frag bank = (8t+g) conflict-free

    const int tid = threadIdx.x, lane = tid & 31, wid = tid >> 5;
    const int g = lane >> 2, t = lane & 3;
    const int warpM = (wid >> 2) * 64, warpN = (wid & 3) * 32;
    const int M0 = blockIdx.y * 128, N0 = blockIdx.x * 128;

    float acc[4][4][4];
    #pragma unroll
    for (int i = 0; i < 4; i++)
        #pragma unroll
        for (int j = 0; j < 4; j++)
            #pragma unroll
            for (int r = 0; r < 4; r++) acc[i][j][r] = 0.f;

    // global loaders: A 128x32 (2 thr/row, 16 floats each), B 32x128 (8 thr/row)
    const int arow = tid >> 1, acolb = (tid & 1) * 16;
    const int brow = tid >> 3, bcolb = (tid & 7) * 16;
    const float* Ap = A + (size_t)(M0 + arow) * K + acolb;
    const float* Bp = B + (size_t)brow * N + N0 + bcolb;

    for (int k0 = 0; k0 < K; k0 += 32) {
        float4 a[4], b[4];
        #pragma unroll
        for (int i = 0; i < 4; i++) a[i] = *(const float4*)(Ap + k0 + i * 4);
        #pragma unroll
        for (int i = 0; i < 4; i++) b[i] = *(const float4*)(Bp + (size_t)k0 * N + i * 4);
        __syncthreads();
        #pragma unroll
        for (int i = 0; i < 4; i++) *(float4*)&As[arow][acolb + i * 4] = a[i];
        #pragma unroll
        for (int i = 0; i < 4; i++) *(float4*)&Bs[brow][bcolb + i * 4] = b[i];
        __syncthreads();

        #pragma unroll
        for (int kk = 0; kk < 4; kk++) {
            const int kb = kk * 8;
            uint32_t Ahi[4][4], Alo[4][4];
            #pragma unroll
            for (int fm = 0; fm < 4; fm++) {
                const int m = warpM + fm * 16;
                tf32_split(As[m + g    ][kb + t    ], Ahi[fm][0], Alo[fm][0]);
                tf32_split(As[m + g + 8][kb + t    ], Ahi[fm][1], Alo[fm][1]);
                tf32_split(As[m + g    ][kb + t + 4], Ahi[fm][2], Alo[fm][2]);
                tf32_split(As[m + g + 8][kb + t + 4], Ahi[fm][3], Alo[fm][3]);
            }
            uint32_t Bhi[4][2], Blo[4][2];
            #pragma unroll
            for (int fn = 0; fn < 4; fn++) {
                const int n = warpN + fn * 8;
                tf32_split(Bs[kb + t    ][n + g], Bhi[fn][0], Blo[fn][0]);
                tf32_split(Bs[kb + t + 4][n + g], Bhi[fn][1], Blo[fn][1]);
            }
            #pragma unroll
            for (int fm = 0; fm < 4; fm++)
                #pragma unroll
                for (int fn = 0; fn < 4; fn++) {
                    mma8(acc[fm][fn], Ahi[fm], Bhi[fn]);
                    mma8(acc[fm][fn], Ahi[fm], Blo[fn]);
                    mma8(acc[fm][fn], Alo[fm], Bhi[fn]);
                }
        }
    }

    // epilogue
    #pragma unroll
    for (int fm = 0; fm < 4; fm++) {
        const int rbase = M0 + warpM + fm * 16 + g;
        #pragma unroll
        for (int half = 0; half < 2; half++) {
            const int row = rbase + half * 8;
            float* crow = C + (size_t)row * N;
            const float* rrow = RES ? (res + (size_t)row * N) : nullptr;
            #pragma unroll
            for (int fn = 0; fn < 4; fn++) {
                const int col = N0 + warpN + fn * 8 + 2 * t;
                float v0 = acc[fm][fn][half * 2 + 0] + __ldg(&bias[col]);
                float v1 = acc[fm][fn][half * 2 + 1] + __ldg(&bias[col + 1]);
                if (RES) {
                    float2 rv = *(const float2*)&rrow[col];
                    v0 += rv.x; v1 += rv.y;
                }
                if (RELU) { v0 = fmaxf(v0, 0.f); v1 = fmaxf(v1, 0.f); }
                *(float2*)&crow[col] = make_float2(v0, v1);
            }
        }
    }
}

// ---------------------------------------------------------------- flash attention (fp32)
// grid (T/32, H, B), 256 thr. BQ=32, BK=64, hd=64. Online softmax.
__global__ __launch_bounds__(256)
void attn_kernel(const float* __restrict__ qkv, const float* __restrict__ amask,
                 float* __restrict__ ctx) {
    const int q0 = blockIdx.x * 32;
    const int h = blockIdx.y, b = blockIdx.z;
    const int tid = threadIdx.x;

    __shared__ float QsT[64][36];        // [d][q]
    __shared__ float KV[64 * 68];        // phase1: K^T [d][k] stride 68; phase3: V [k][d] stride 68
    __shared__ float Ss[32][68];         // scores / probs
    __shared__ float row_m[32], row_l[32], row_a[32];
    __shared__ float madd[64];

    // load Q^T
    for (int idx = tid; idx < 32 * 64; idx += 256) {
        int q = idx >> 6, d = idx & 63;
        QsT[d][q] = qkv[(size_t)(b * TT + q0 + q) * (3 * DD) + h * 64 + d];
    }
    if (tid < 32) { row_m[tid] = -3.0e38f; row_l[tid] = 0.f; }

    float o[2][4] = {{0.f,0.f,0.f,0.f},{0.f,0.f,0.f,0.f}};
    const int oq = (tid >> 4) * 2, od = (tid & 15) * 4;   // O / S microtile mapping
    const int srow = tid >> 3, sseg = tid & 7;            // softmax mapping (8 lanes / row)
    __syncthreads();

    const int kend = q0 + 32;
    for (int k0 = 0; k0 < kend; k0 += 64) {
        // ---- load K^T and additive mask ----
        for (int idx = tid; idx < 64 * 64; idx += 256) {
            int kt = idx >> 6, d = idx & 63;
            KV[d * 68 + kt] = qkv[(size_t)(b * TT + k0 + kt) * (3 * DD) + DD + h * 64 + d];
        }
        if (tid < 64) madd[tid] = (1.0f - amask[b * TT + k0 + tid]) * MASK_BIAS;
        __syncthreads();

        // ---- S = Q @ K^T (2x4 microtile) ----
        float s[2][4] = {{0.f,0.f,0.f,0.f},{0.f,0.f,0.f,0.f}};
        #pragma unroll 8
        for (int d = 0; d < 64; d++) {
            float2 qv = *(const float2*)&QsT[d][oq];
            float4 kv = *(const float4*)&KV[d * 68 + od];
            s[0][0] += qv.x * kv.x; s[0][1] += qv.x * kv.y;
            s[0][2] += qv.x * kv.z; s[0][3] += qv.x * kv.w;
            s[1][0] += qv.y * kv.x; s[1][1] += qv.y * kv.y;
            s[1][2] += qv.y * kv.z; s[1][3] += qv.y * kv.w;
        }
        // mask + scale + store
        #pragma unroll
        for (int i = 0; i < 2; i++) {
            int qg = q0 + oq + i;
            float vv[4];
            #pragma unroll
            for (int j = 0; j < 4; j++) {
                int kg = k0 + od + j;
                float v = (kg <= qg) ? s[i][j] * 0.125f : MASK_BIAS;
                vv[j] = v + madd[od + j];
            }
            *(float4*)&Ss[oq + i][od] = make_float4(vv[0], vv[1], vv[2], vv[3]);
        }
        __syncthreads();

        // ---- online softmax (8 lanes per row) ----
        {
            float* sr = &Ss[srow][sseg * 8];
            float lm = sr[0];
            #pragma unroll
            for (int j = 1; j < 8; j++) lm = fmaxf(lm, sr[j]);
            lm = fmaxf(lm, __shfl_xor_sync(0xffffffffu, lm, 1, 8));
            lm = fmaxf(lm, __shfl_xor_sync(0xffffffffu, lm, 2, 8));
            lm = fmaxf(lm, __shfl_xor_sync(0xffffffffu, lm, 4, 8));
            float m_old = row_m[srow];
            float m_new = fmaxf(m_old, lm);
            float ls = 0.f;
            #pragma unroll
            for (int j = 0; j < 8; j++) {
                float p = __expf(sr[j] - m_new);
                sr[j] = p;
                ls += p;
            }
            ls += __shfl_xor_sync(0xffffffffu, ls, 1, 8);
            ls += __shfl_xor_sync(0xffffffffu, ls, 2, 8);
            ls += __shfl_xor_sync(0xffffffffu, ls, 4, 8);
            if (sseg == 0) {
                float alpha = __expf(m_old - m_new);
                row_l[srow] = row_l[srow] * alpha + ls;
                row_m[srow] = m_new;
                row_a[srow] = alpha;
            }
        }
        __syncthreads();

        // ---- rescale O; load V (overwrites KV) ----
        {
            float a0 = row_a[oq], a1 = row_a[oq + 1];
            #pragma unroll
            for (int j = 0; j < 4; j++) { o[0][j] *= a0; o[1][j] *= a1; }
        }
        for (int idx = tid; idx < 64 * 64; idx += 256) {
            int kt = idx >> 6, d = idx & 63;
            KV[kt * 68 + d] = qkv[(size_t)(b * TT + k0 + kt) * (3 * DD) + 2 * DD + h * 64 + d];
        }
        __syncthreads();

        // ---- O += P @ V ----
        #pragma unroll 8
        for (int k = 0; k < 64; k++) {
            float p0 = Ss[oq][k], p1 = Ss[oq + 1][k];
            float4 vv = *(const float4*)&KV[k * 68 + od];
            o[0][0] += p0 * vv.x; o[0][1] += p0 * vv.y;
            o[0][2] += p0 * vv.z; o[0][3] += p0 * vv.w;
            o[1][0] += p1 * vv.x; o[1][1] += p1 * vv.y;
            o[1][2] += p1 * vv.z; o[1][3] += p1 * vv.w;
        }
        __syncthreads();
    }

    float inv0 = 1.f / row_l[oq];
    float inv1 = 1.f / row_l[oq + 1];
    float* c0 = ctx + (size_t)(b * TT + q0 + oq) * DD + h * 64 + od;
    float* c1 = ctx + (size_t)(b * TT + q0 + oq + 1) * DD + h * 64 + od;
    *(float4*)c0 = make_float4(o[0][0]*inv0, o[0][1]*inv0, o[0][2]*inv0, o[0][3]*inv0);
    *(float4*)c1 = make_float4(o[1][0]*inv1, o[1][1]*inv1, o[1][2]*inv1, o[1][3]*inv1);
}

// ---------------------------------------------------------------- launch
extern "C" void kernel_launch(void* const* d_in, const int* in_sizes, int n_in,
                              void* d_out, int out_size) {
    const float* emb   = (const float*)d_in[0];
    const float* amask = (const float*)d_in[1];
    const float* ln1w  = (const float*)d_in[2];
    const float* ln1b  = (const float*)d_in[3];
    const float* attnw = (const float*)d_in[4];
    const float* attnb = (const float*)d_in[5];
    const float* projw = (const float*)d_in[6];
    const float* projb = (const float*)d_in[7];
    const float* ln2w  = (const float*)d_in[8];
    const float* ln2b  = (const float*)d_in[9];
    const float* fcw   = (const float*)d_in[10];
    const float* fcb   = (const float*)d_in[11];
    const float* fcpw  = (const float*)d_in[12];
    const float* fcpb  = (const float*)d_in[13];
    const float* lnfw  = (const float*)d_in[14];
    const float* lnfb  = (const float*)d_in[15];
    float* out = (float*)d_out;

    float *H, *X, *QKV, *CTX, *FF;
    cudaGetSymbolAddress((void**)&H,   g_H);
    cudaGetSymbolAddress((void**)&X,   g_X);
    cudaGetSymbolAddress((void**)&QKV, g_QKV);
    cudaGetSymbolAddress((void**)&CTX, g_CTX);
    cudaGetSymbolAddress((void**)&FF,  g_FF);

    const int n4 = (MROWS * DD) / 4;
    copy_kernel<<<(n4 + 255) / 256, 256>>>((const float4*)emb, (float4*)H, n4);

    for (int l = 0; l < LL; l++) {
        const size_t wq = (size_t)l * DD * 3 * DD;
        const size_t wp = (size_t)l * DD * DD;
        const size_t wf = (size_t)l * DD * II;
        const size_t wg = (size_t)l * II * DD;

        ln_kernel<<<MROWS, 256>>>(H, ln1w + l * DD, ln1b + l * DD, X);
        gemm_tc_kernel<false, false><<<dim3(3 * DD / 128, MROWS / 128), 256>>>(
            X, attnw + wq, attnb + (size_t)l * 3 * DD, nullptr, QKV, 3 * DD, DD);
        attn_kernel<<<dim3(TT / 32, HH, BB), 256>>>(QKV, amask, CTX);
        gemm_tc_kernel<true, false><<<dim3(DD / 128, MROWS / 128), 256>>>(
            CTX, projw + wp, projb + (size_t)l * DD, H, H, DD, DD);
        ln_kernel<<<MROWS, 256>>>(H, ln2w + l * DD, ln2b + l * DD, X);
        gemm_tc_kernel<false, true><<<dim3(II / 128, MROWS / 128), 256>>>(
            X, fcw + wf, fcb + (size_t)l * II, nullptr, FF, II, DD);
        gemm_tc_kernel<true, false><<<dim3(DD / 128, MROWS / 128), 256>>>(
            FF, fcpw + wg, fcpb + (size_t)l * DD, H, H, DD, II);
    }
    ln_kernel<<<MROWS, 256>>>(H, lnfw, lnfb, out);
}

// round 6
// speedup vs baseline: 1.8869x; 1.8566x over previous
#include <cuda_runtime.h>
#include <cuda_bf16.h>
#include <math.h>
#include <stdint.h>

#define BB 2
#define TT 2048
#define DD 1024
#define HH 16
#define LL 8
#define II 4096
#define MROWS (BB*TT)          // 4096
#define MASK_BIAS (-10000.0f)

// -------- scratch (no allocations allowed) --------
static __device__ float g_H  [(size_t)MROWS*DD];          // residual stream (f32)
static __device__ float g_QKV[(size_t)MROWS*3*DD];        // qkv (f32)
static __device__ __nv_bfloat16 g_Ah[(size_t)MROWS*II];   // activation split hi (X / CTX)
static __device__ __nv_bfloat16 g_Al[(size_t)MROWS*II];   // activation split lo
static __device__ __nv_bfloat16 g_Fh[(size_t)MROWS*II];   // FF split hi
static __device__ __nv_bfloat16 g_Fl[(size_t)MROWS*II];   // FF split lo
static __device__ __nv_bfloat16 g_Wh[(size_t)II*DD];      // weight^T split hi [N x K]
static __device__ __nv_bfloat16 g_Wl[(size_t)II*DD];      // weight^T split lo

// ---------------------------------------------------------------- helpers
__device__ __forceinline__ uint32_t smem_u32(const void* p) {
    return (uint32_t)__cvta_generic_to_shared(p);
}

__device__ __forceinline__ void split_bf16(float x, __nv_bfloat16& h, __nv_bfloat16& l) {
    h = __float2bfloat16(x);
    l = __float2bfloat16(x - __bfloat162float(h));
}

__device__ __forceinline__ void mma_bf16(float* c, const uint32_t* a, const uint32_t* b) {
    asm volatile(
        "mma.sync.aligned.m16n8k16.row.col.f32.bf16.bf16.f32 "
        "{%0,%1,%2,%3},{%4,%5,%6,%7},{%8,%9},{%0,%1,%2,%3};"
        : "+f"(c[0]), "+f"(c[1]), "+f"(c[2]), "+f"(c[3])
        : "r"(a[0]), "r"(a[1]), "r"(a[2]), "r"(a[3]), "r"(b[0]), "r"(b[1]));
}

__device__ __forceinline__ void cpasync16(uint32_t dst, const void* src) {
    asm volatile("cp.async.cg.shared.global [%0], [%1], 16;" :: "r"(dst), "l"(src));
}
__device__ __forceinline__ void cp_commit() { asm volatile("cp.async.commit_group;"); }
__device__ __forceinline__ void cp_wait1()  { asm volatile("cp.async.wait_group 1;"); }
__device__ __forceinline__ void cp_wait0()  { asm volatile("cp.async.wait_group 0;"); }

// ---------------------------------------------------------------- copy
__global__ void copy_kernel(const float4* __restrict__ src, float4* __restrict__ dst, int n4) {
    int i = blockIdx.x * blockDim.x + threadIdx.x;
    if (i < n4) dst[i] = src[i];
}

// ---------------------------------------------------------------- layernorm core (256 thr, D=1024)
__device__ __forceinline__ float4 ln_core(const float* __restrict__ in,
                                          const float* __restrict__ w,
                                          const float* __restrict__ bsc, int row, int t) {
    const float4* x4 = (const float4*)(in + (size_t)row * DD);
    float4 v = x4[t];
    float s = v.x + v.y + v.z + v.w;
    float q = v.x*v.x + v.y*v.y + v.z*v.z + v.w*v.w;
    #pragma unroll
    for (int o = 16; o; o >>= 1) {
        s += __shfl_xor_sync(0xffffffffu, s, o);
        q += __shfl_xor_sync(0xffffffffu, q, o);
    }
    __shared__ float ss[8], sq[8];
    __shared__ float red[2];
    int wid = t >> 5, lane = t & 31;
    if (lane == 0) { ss[wid] = s; sq[wid] = q; }
    __syncthreads();
    if (t == 0) {
        float S = 0.f, Q = 0.f;
        #pragma unroll
        for (int i = 0; i < 8; i++) { S += ss[i]; Q += sq[i]; }
        float mean = S * (1.0f / DD);
        float var  = Q * (1.0f / DD) - mean * mean;
        red[0] = mean;
        red[1] = rsqrtf(var + 1e-5f);
    }
    __syncthreads();
    float mean = red[0], inv = red[1];
    float4 wv = ((const float4*)w)[t];
    float4 bv = ((const float4*)bsc)[t];
    float4 o;
    o.x = (v.x - mean) * inv * wv.x + bv.x;
    o.y = (v.y - mean) * inv * wv.y + bv.y;
    o.z = (v.z - mean) * inv * wv.z + bv.z;
    o.w = (v.w - mean) * inv * wv.w + bv.w;
    return o;
}

__global__ void ln_kernel(const float* __restrict__ in, const float* __restrict__ w,
                          const float* __restrict__ bsc, float* __restrict__ out) {
    int row = blockIdx.x, t = threadIdx.x;
    float4 o = ln_core(in, w, bsc, row, t);
    ((float4*)(out + (size_t)row * DD))[t] = o;
}

__global__ void ln_split_kernel(const float* __restrict__ in, const float* __restrict__ w,
                                const float* __restrict__ bsc,
                                __nv_bfloat16* __restrict__ oh, __nv_bfloat16* __restrict__ ol) {
    int row = blockIdx.x, t = threadIdx.x;
    float4 o = ln_core(in, w, bsc, row, t);
    __nv_bfloat16 h0,h1,h2,h3,l0,l1,l2,l3;
    split_bf16(o.x,h0,l0); split_bf16(o.y,h1,l1); split_bf16(o.z,h2,l2); split_bf16(o.w,h3,l3);
    size_t idx = (size_t)row * DD + t * 4;
    *(__nv_bfloat162*)(oh + idx)     = __nv_bfloat162{h0,h1};
    *(__nv_bfloat162*)(oh + idx + 2) = __nv_bfloat162{h2,h3};
    *(__nv_bfloat162*)(ol + idx)     = __nv_bfloat162{l0,l1};
    *(__nv_bfloat162*)(ol + idx + 2) = __nv_bfloat162{l2,l3};
}

// ---------------------------------------------------------------- weight transpose + split
// W: [K x N] f32 row-major  ->  Th/Tl: [N x K] bf16
__global__ void splitT_kernel(const float* __restrict__ W, __nv_bfloat16* __restrict__ Th,
                              __nv_bfloat16* __restrict__ Tl, int K, int N) {
    __shared__ float t[32][33];
    int k0 = blockIdx.y * 32, n0 = blockIdx.x * 32;
    int tx = threadIdx.x & 31, ty = threadIdx.x >> 5;   // 8 rows per pass
    #pragma unroll
    for (int i = 0; i < 4; i++) {
        int r = ty + i * 8;
        t[r][tx] = W[(size_t)(k0 + r) * N + n0 + tx];
    }
    __syncthreads();
    #pragma unroll
    for (int i = 0; i < 4; i++) {
        int r = ty + i * 8;
        float v = t[tx][r];                 // = W[k0+tx][n0+r]
        __nv_bfloat16 h, l;
        split_bf16(v, h, l);
        size_t o = (size_t)(n0 + r) * K + k0 + tx;
        Th[o] = h; Tl[o] = l;
    }
}

// ---------------------------------------------------------------- bf16x3 mma.sync GEMM
// C[m][n] = sum_k A[m][k]*W[k][n] + bias (+res)(+relu). B operand = W^T [N x K] bf16.
// CTA 128x128, BK=64, 8 warps (2x4), warp tile 64x32, double-buffered cp.async.
#define SROWB   144                       // bytes per smem row (64 bf16 + 8 pad)
#define TILEB   (128 * SROWB)             // 18432 B
#define STAGEB  (4 * TILEB)               // Ah, Al, Bh, Bl
#define GSMEM   (2 * STAGEB)              // 147456 B

template<bool RES, bool RELU, bool SPLITOUT>
__global__ __launch_bounds__(256)
void gemm_mma(const __nv_bfloat16* __restrict__ Ah, const __nv_bfloat16* __restrict__ Al,
              const __nv_bfloat16* __restrict__ Bh, const __nv_bfloat16* __restrict__ Bl,
              const float* __restrict__ bias, const float* __restrict__ res,
              float* __restrict__ C, __nv_bfloat16* __restrict__ Ch, __nv_bfloat16* __restrict__ Cl,
              int N, int K) {
    extern __shared__ char sm[];
    const int tid = threadIdx.x, lane = tid & 31, wid = tid >> 5;
    const int g = lane >> 2, t = lane & 3;
    const int warpM = (wid >> 2) * 64, warpN = (wid & 3) * 32;
    const int M0 = blockIdx.y * 128, N0 = blockIdx.x * 128;

    const __nv_bfloat16* srcs[4] = {Ah, Al, Bh, Bl};
    const int bases[4] = {M0, M0, N0, N0};

    // async copy of one K64 chunk into stage s
    auto issue = [&](int c, int s) {
        const int k0 = c << 6;
        #pragma unroll
        for (int arr = 0; arr < 4; arr++) {
            char* dstb = sm + s * STAGEB + arr * TILEB;
            const __nv_bfloat16* srcb = srcs[arr] + (size_t)bases[arr] * K + k0;
            #pragma unroll
            for (int i = 0; i < 4; i++) {
                int cc = i * 256 + tid;
                int r = cc >> 3, j = cc & 7;
                cpasync16(smem_u32(dstb + r * SROWB + j * 16),
                          srcb + (size_t)r * K + j * 8);
            }
        }
    };

    float acc[4][4][4];
    #pragma unroll
    for (int i = 0; i < 4; i++)
        #pragma unroll
        for (int j = 0; j < 4; j++)
            #pragma unroll
            for (int r = 0; r < 4; r++) acc[i][j][r] = 0.f;

    const int nch = K >> 6;
    issue(0, 0); cp_commit();

    for (int c = 0; c < nch; ++c) {
        if (c + 1 < nch) { issue(c + 1, (c + 1) & 1); cp_commit(); cp_wait1(); }
        else cp_wait0();
        __syncthreads();

        const char* base = sm + (c & 1) * STAGEB;
        #pragma unroll
        for (int ks = 0; ks < 4; ks++) {
            const int kb = ks * 16;
            uint32_t ah[4][4], al[4][4];
            #pragma unroll
            for (int fm = 0; fm < 4; fm++) {
                const char* rp = base + (warpM + fm * 16 + g) * SROWB + (kb + 2 * t) * 2;
                ah[fm][0] = *(const uint32_t*)(rp);
                ah[fm][1] = *(const uint32_t*)(rp + 8 * SROWB);
                ah[fm][2] = *(const uint32_t*)(rp + 16);
                ah[fm][3] = *(const uint32_t*)(rp + 8 * SROWB + 16);
                const char* rq = rp + TILEB;
                al[fm][0] = *(const uint32_t*)(rq);
                al[fm][1] = *(const uint32_t*)(rq + 8 * SROWB);
                al[fm][2] = *(const uint32_t*)(rq + 16);
                al[fm][3] = *(const uint32_t*)(rq + 8 * SROWB + 16);
            }
            uint32_t bh[4][2], bl[4][2];
            #pragma unroll
            for (int fn = 0; fn < 4; fn++) {
                const char* rp = base + 2 * TILEB + (warpN + fn * 8 + g) * SROWB + (kb + 2 * t) * 2;
                bh[fn][0] = *(const uint32_t*)(rp);
                bh[fn][1] = *(const uint32_t*)(rp + 16);
                bl[fn][0] = *(const uint32_t*)(rp + TILEB);
                bl[fn][1] = *(const uint32_t*)(rp + TILEB + 16);
            }
            #pragma unroll
            for (int fm = 0; fm < 4; fm++)
                #pragma unroll
                for (int fn = 0; fn < 4; fn++) {
                    mma_bf16(acc[fm][fn], ah[fm], bh[fn]);
                    mma_bf16(acc[fm][fn], ah[fm], bl[fn]);
                    mma_bf16(acc[fm][fn], al[fm], bh[fn]);
                }
        }
        __syncthreads();
    }

    // epilogue
    #pragma unroll
    for (int fm = 0; fm < 4; fm++) {
        const int rbase = M0 + warpM + fm * 16 + g;
        #pragma unroll
        for (int half = 0; half < 2; half++) {
            const int row = rbase + half * 8;
            #pragma unroll
            for (int fn = 0; fn < 4; fn++) {
                const int col = N0 + warpN + fn * 8 + 2 * t;
                float v0 = acc[fm][fn][half * 2 + 0] + __ldg(&bias[col]);
                float v1 = acc[fm][fn][half * 2 + 1] + __ldg(&bias[col + 1]);
                if (RES) {
                    float2 rv = *(const float2*)(res + (size_t)row * N + col);
                    v0 += rv.x; v1 += rv.y;
                }
                if (RELU) { v0 = fmaxf(v0, 0.f); v1 = fmaxf(v1, 0.f); }
                if (SPLITOUT) {
                    __nv_bfloat16 h0,h1,l0,l1;
                    split_bf16(v0, h0, l0);
                    split_bf16(v1, h1, l1);
                    *(__nv_bfloat162*)(Ch + (size_t)row * N + col) = __nv_bfloat162{h0, h1};
                    *(__nv_bfloat162*)(Cl + (size_t)row * N + col) = __nv_bfloat162{l0, l1};
                } else {
                    *(float2*)(C + (size_t)row * N + col) = make_float2(v0, v1);
                }
            }
        }
    }
}

// ---------------------------------------------------------------- flash attention (fp32, split-bf16 out)
__global__ __launch_bounds__(256)
void attn_kernel(const float* __restrict__ qkv, const float* __restrict__ amask,
                 __nv_bfloat16* __restrict__ ch, __nv_bfloat16* __restrict__ cl) {
    const int q0 = blockIdx.x * 32;
    const int h = blockIdx.y, b = blockIdx.z;
    const int tid = threadIdx.x;

    __shared__ float QsT[64][36];
    __shared__ float KV[64 * 68];
    __shared__ float Ss[32][68];
    __shared__ float row_m[32], row_l[32], row_a[32];
    __shared__ float madd[64];

    for (int idx = tid; idx < 32 * 64; idx += 256) {
        int q = idx >> 6, d = idx & 63;
        QsT[d][q] = qkv[(size_t)(b * TT + q0 + q) * (3 * DD) + h * 64 + d];
    }
    if (tid < 32) { row_m[tid] = -3.0e38f; row_l[tid] = 0.f; }

    float o[2][4] = {{0.f,0.f,0.f,0.f},{0.f,0.f,0.f,0.f}};
    const int oq = (tid >> 4) * 2, od = (tid & 15) * 4;
    const int srow = tid >> 3, sseg = tid & 7;
    __syncthreads();

    const int kend = q0 + 32;
    for (int k0 = 0; k0 < kend; k0 += 64) {
        for (int idx = tid; idx < 64 * 64; idx += 256) {
            int kt = idx >> 6, d = idx & 63;
            KV[d * 68 + kt] = qkv[(size_t)(b * TT + k0 + kt) * (3 * DD) + DD + h * 64 + d];
        }
        if (tid < 64) madd[tid] = (1.0f - amask[b * TT + k0 + tid]) * MASK_BIAS;
        __syncthreads();

        float s[2][4] = {{0.f,0.f,0.f,0.f},{0.f,0.f,0.f,0.f}};
        #pragma unroll 8
        for (int d = 0; d < 64; d++) {
            float2 qv = *(const float2*)&QsT[d][oq];
            float4 kv = *(const float4*)&KV[d * 68 + od];
            s[0][0] += qv.x * kv.x; s[0][1] += qv.x * kv.y;
            s[0][2] += qv.x * kv.z; s[0][3] += qv.x * kv.w;
            s[1][0] += qv.y * kv.x; s[1][1] += qv.y * kv.y;
            s[1][2] += qv.y * kv.z; s[1][3] += qv.y * kv.w;
        }
        #pragma unroll
        for (int i = 0; i < 2; i++) {
            int qg = q0 + oq + i;
            float vv[4];
            #pragma unroll
            for (int j = 0; j < 4; j++) {
                int kg = k0 + od + j;
                float v = (kg <= qg) ? s[i][j] * 0.125f : MASK_BIAS;
                vv[j] = v + madd[od + j];
            }
            *(float4*)&Ss[oq + i][od] = make_float4(vv[0], vv[1], vv[2], vv[3]);
        }
        __syncthreads();

        {
            float* sr = &Ss[srow][sseg * 8];
            float lm = sr[0];
            #pragma unroll
            for (int j = 1; j < 8; j++) lm = fmaxf(lm, sr[j]);
            lm = fmaxf(lm, __shfl_xor_sync(0xffffffffu, lm, 1, 8));
            lm = fmaxf(lm, __shfl_xor_sync(0xffffffffu, lm, 2, 8));
            lm = fmaxf(lm, __shfl_xor_sync(0xffffffffu, lm, 4, 8));
            float m_old = row_m[srow];
            float m_new = fmaxf(m_old, lm);
            float ls = 0.f;
            #pragma unroll
            for (int j = 0; j < 8; j++) {
                float p = __expf(sr[j] - m_new);
                sr[j] = p;
                ls += p;
            }
            ls += __shfl_xor_sync(0xffffffffu, ls, 1, 8);
            ls += __shfl_xor_sync(0xffffffffu, ls, 2, 8);
            ls += __shfl_xor_sync(0xffffffffu, ls, 4, 8);
            if (sseg == 0) {
                float alpha = __expf(m_old - m_new);
                row_l[srow] = row_l[srow] * alpha + ls;
                row_m[srow] = m_new;
                row_a[srow] = alpha;
            }
        }
        __syncthreads();

        {
            float a0 = row_a[oq], a1 = row_a[oq + 1];
            #pragma unroll
            for (int j = 0; j < 4; j++) { o[0][j] *= a0; o[1][j] *= a1; }
        }
        for (int idx = tid; idx < 64 * 64; idx += 256) {
            int kt = idx >> 6, d = idx & 63;
            KV[kt * 68 + d] = qkv[(size_t)(b * TT + k0 + kt) * (3 * DD) + 2 * DD + h * 64 + d];
        }
        __syncthreads();

        #pragma unroll 8
        for (int k = 0; k < 64; k++) {
            float p0 = Ss[oq][k], p1 = Ss[oq + 1][k];
            float4 vv = *(const float4*)&KV[k * 68 + od];
            o[0][0] += p0 * vv.x; o[0][1] += p0 * vv.y;
            o[0][2] += p0 * vv.z; o[0][3] += p0 * vv.w;
            o[1][0] += p1 * vv.x; o[1][1] += p1 * vv.y;
            o[1][2] += p1 * vv.z; o[1][3] += p1 * vv.w;
        }
        __syncthreads();
    }

    float inv0 = 1.f / row_l[oq];
    float inv1 = 1.f / row_l[oq + 1];
    #pragma unroll
    for (int i = 0; i < 2; i++) {
        float inv = i ? inv1 : inv0;
        size_t base = (size_t)(b * TT + q0 + oq + i) * DD + h * 64 + od;
        __nv_bfloat16 h0,h1,h2,h3,l0,l1,l2,l3;
        split_bf16(o[i][0] * inv, h0, l0);
        split_bf16(o[i][1] * inv, h1, l1);
        split_bf16(o[i][2] * inv, h2, l2);
        split_bf16(o[i][3] * inv, h3, l3);
        *(__nv_bfloat162*)(ch + base)     = __nv_bfloat162{h0, h1};
        *(__nv_bfloat162*)(ch + base + 2) = __nv_bfloat162{h2, h3};
        *(__nv_bfloat162*)(cl + base)     = __nv_bfloat162{l0, l1};
        *(__nv_bfloat162*)(cl + base + 2) = __nv_bfloat162{l2, l3};
    }
}

// ---------------------------------------------------------------- launch
extern "C" void kernel_launch(void* const* d_in, const int* in_sizes, int n_in,
                              void* d_out, int out_size) {
    const float* emb   = (const float*)d_in[0];
    const float* amask = (const float*)d_in[1];
    const float* ln1w  = (const float*)d_in[2];
    const float* ln1b  = (const float*)d_in[3];
    const float* attnw = (const float*)d_in[4];
    const float* attnb = (const float*)d_in[5];
    const float* projw = (const float*)d_in[6];
    const float* projb = (const float*)d_in[7];
    const float* ln2w  = (const float*)d_in[8];
    const float* ln2b  = (const float*)d_in[9];
    const float* fcw   = (const float*)d_in[10];
    const float* fcb   = (const float*)d_in[11];
    const float* fcpw  = (const float*)d_in[12];
    const float* fcpb  = (const float*)d_in[13];
    const float* lnfw  = (const float*)d_in[14];
    const float* lnfb  = (const float*)d_in[15];
    float* out = (float*)d_out;

    float *H, *QKV;
    __nv_bfloat16 *Ah, *Al, *Fh, *Fl, *Wh, *Wl;
    cudaGetSymbolAddress((void**)&H,   g_H);
    cudaGetSymbolAddress((void**)&QKV, g_QKV);
    cudaGetSymbolAddress((void**)&Ah,  g_Ah);
    cudaGetSymbolAddress((void**)&Al,  g_Al);
    cudaGetSymbolAddress((void**)&Fh,  g_Fh);
    cudaGetSymbolAddress((void**)&Fl,  g_Fl);
    cudaGetSymbolAddress((void**)&Wh,  g_Wh);
    cudaGetSymbolAddress((void**)&Wl,  g_Wl);

    cudaFuncSetAttribute(gemm_mma<false,false,false>, cudaFuncAttributeMaxDynamicSharedMemorySize, GSMEM);
    cudaFuncSetAttribute(gemm_mma<true, false,false>, cudaFuncAttributeMaxDynamicSharedMemorySize, GSMEM);
    cudaFuncSetAttribute(gemm_mma<false,true, true >, cudaFuncAttributeMaxDynamicSharedMemorySize, GSMEM);

    const int n4 = (MROWS * DD) / 4;
    copy_kernel<<<(n4 + 255) / 256, 256>>>((const float4*)emb, (float4*)H, n4);

    for (int l = 0; l < LL; l++) {
        const size_t wq = (size_t)l * DD * 3 * DD;
        const size_t wp = (size_t)l * DD * DD;
        const size_t wf = (size_t)l * DD * II;
        const size_t wg = (size_t)l * II * DD;

        // --- attention ---
        ln_split_kernel<<<MROWS, 256>>>(H, ln1w + l * DD, ln1b + l * DD, Ah, Al);
        splitT_kernel<<<dim3(3 * DD / 32, DD / 32), 256>>>(attnw + wq, Wh, Wl, DD, 3 * DD);
        gemm_mma<false,false,false><<<dim3(3 * DD / 128, MROWS / 128), 256, GSMEM>>>(
            Ah, Al, Wh, Wl, attnb + (size_t)l * 3 * DD, nullptr, QKV, nullptr, nullptr, 3 * DD, DD);
        attn_kernel<<<dim3(TT / 32, HH, BB), 256>>>(QKV, amask, Ah, Al);
        splitT_kernel<<<dim3(DD / 32, DD / 32), 256>>>(projw + wp, Wh, Wl, DD, DD);
        gemm_mma<true,false,false><<<dim3(DD / 128, MROWS / 128), 256, GSMEM>>>(
            Ah, Al, Wh, Wl, projb + (size_t)l * DD, H, H, nullptr, nullptr, DD, DD);

        // --- feed-forward ---
        ln_split_kernel<<<MROWS, 256>>>(H, ln2w + l * DD, ln2b + l * DD, Ah, Al);
        splitT_kernel<<<dim3(II / 32, DD / 32), 256>>>(fcw + wf, Wh, Wl, DD, II);
        gemm_mma<false,true,true><<<dim3(II / 128, MROWS / 128), 256, GSMEM>>>(
            Ah, Al, Wh, Wl, fcb + (size_t)l * II, nullptr, nullptr, Fh, Fl, II, DD);
        splitT_kernel<<<dim3(DD / 32, II / 32), 256>>>(fcpw + wg, Wh, Wl, II, DD);
        gemm_mma<true,false,false><<<dim3(DD / 128, MROWS / 128), 256, GSMEM>>>(
            Fh, Fl, Wh, Wl, fcpb + (size_t)l * DD, H, H, nullptr, nullptr, DD, II);
    }
    ln_kernel<<<MROWS, 256>>>(H, lnfw, lnfb, out);
}